// round 1
// baseline (speedup 1.0000x reference)
#include <cuda_runtime.h>
#include <math.h>

#define BATCH 16
#define NPTS  2048
#define KNN   10

__device__ float g_loss[BATCH * NPTS];

__device__ __forceinline__ void sort3(float& a, float& b, float& c) {
    float lo = fminf(a, b), hi = fmaxf(a, b);
    float l0 = fminf(lo, c);
    float l2 = fmaxf(hi, c);
    float l1 = fmaxf(lo, fminf(hi, c));
    a = l0; b = l1; c = l2;
}

__global__ __launch_bounds__(256) void knn_loss_kernel(const float* __restrict__ src,
                                                       const float* __restrict__ tgt) {
    extern __shared__ float sm[];
    float* sx  = sm;
    float* sy  = sm + NPTS;
    float* sz  = sm + 2 * NPTS;
    float* sq  = sm + 3 * NPTS;
    float* txs = sm + 4 * NPTS;
    float* tys = sm + 5 * NPTS;
    float* tzs = sm + 6 * NPTS;

    const int b     = blockIdx.x >> 3;
    const int chunk = blockIdx.x & 7;
    const int tid   = threadIdx.x;

    const float* sb = src + b * 3 * NPTS;
    const float* tb = tgt + b * 3 * NPTS;
    for (int i = tid; i < NPTS; i += 256) {
        float x = sb[i], y = sb[NPTS + i], z = sb[2 * NPTS + i];
        sx[i] = x; sy[i] = y; sz[i] = z;
        sq[i] = x * x + y * y + z * z;          // matches jnp.sum(xt*xt, -1)
        txs[i] = tb[i]; tys[i] = tb[NPTS + i]; tzs[i] = tb[2 * NPTS + i];
    }
    __syncthreads();

    const float FINF = __int_as_float(0x7f800000);
    const int n = chunk * 256 + tid;

    const float xn = sx[n], yn = sy[n], zn = sz[n];
    const float sqn = sq[n];

    // ---- Phase 1: top-10 smallest key = d2 + 1e-7 with key >= 0.1 (ref's masking),
    // ascending-scan + strict-< insertion reproduces top_k's lower-index tie-break.
    float kb[KNN];
    int   ib[KNN];
#pragma unroll
    for (int i = 0; i < KNN; i++) { kb[i] = FINF; ib[i] = 0; }

#pragma unroll 4
    for (int m = 0; m < NPTS; ++m) {
        float dot = xn * sx[m] + yn * sy[m] + zn * sz[m];
        float d2  = (sqn + sq[m]) - 2.0f * dot;   // ref: sq_n + sq_m - 2*einsum
        float key = d2 + 1e-7f;                   // ref: distance = -(d2+1e-7)
        if (key >= 0.1f && key < kb[KNN - 1]) {   // excluded iff distance > -0.1 <=> key < 0.1
            kb[KNN - 1] = key; ib[KNN - 1] = m;
#pragma unroll
            for (int s = KNN - 1; s > 0; --s) {
                if (kb[s] < kb[s - 1]) {
                    float tk = kb[s]; kb[s] = kb[s - 1]; kb[s - 1] = tk;
                    int   ti = ib[s]; ib[s] = ib[s - 1]; ib[s - 1] = ti;
                } else break;
            }
        }
    }

    // ---- Phase 2: gather 10 neighbors (src & tgt) into registers
    float nsx[KNN], nsy[KNN], nsz[KNN], ntx[KNN], nty[KNN], ntz[KNN];
#pragma unroll
    for (int i = 0; i < KNN; i++) {
        int id = ib[i];
        nsx[i] = sx[id]; nsy[i] = sy[id]; nsz[i] = sz[id];
        ntx[i] = txs[id]; nty[i] = tys[id]; ntz[i] = tzs[id];
    }
    const float xtn = txs[n], ytn = tys[n], ztn = tzs[n];

    // self->neighbor squared distances (direct diff form, as in get_tri)
    float ds0[KNN], dt0[KNN];
#pragma unroll
    for (int i = 0; i < KNN; i++) {
        float dx = xn - nsx[i], dy = yn - nsy[i], dz = zn - nsz[i];
        ds0[i] = dx * dx + dy * dy + dz * dz;
        float ex = xtn - ntx[i], ey = ytn - nty[i], ez = ztn - ntz[i];
        dt0[i] = ex * ex + ey * ey + ez * ez;
    }

    // 45 pairs; keep 10 smallest losses (multiset -> tie-break free)
    float lb[KNN];
#pragma unroll
    for (int i = 0; i < KNN; i++) lb[i] = FINF;

#pragma unroll
    for (int i = 0; i < KNN; i++) {
#pragma unroll
        for (int j = i + 1; j < KNN; j++) {
            float dx = nsx[i] - nsx[j], dy = nsy[i] - nsy[j], dz = nsz[i] - nsz[j];
            float bs = dx * dx + dy * dy + dz * dz;
            float l0 = ds0[i], l1 = bs, l2 = ds0[j];
            sort3(l0, l1, l2);

            float ex = ntx[i] - ntx[j], ey = nty[i] - nty[j], ez = ntz[i] - ntz[j];
            float bt = ex * ex + ey * ey + ez * ez;
            float m0 = dt0[i], m1 = bt, m2 = dt0[j];
            sort3(m0, m1, m2);
            m0 += 1e-6f; m1 += 1e-6f; m2 += 1e-6f;   // length_tgt = sort(tri) + EPS

            float e0 = l0 - m0, e1 = l1 - m1, e2 = l2 - m2;
            float num = e0 * e0 + e1 * e1 + e2 * e2;
            float s0 = l0 + m0, s1 = l1 + m1, s2 = l2 + m2;
            float den = s0 * s0 + s1 * s1 + s2 * s2;
            float loss = num / den;

            if (loss < lb[KNN - 1]) {
                lb[KNN - 1] = loss;
#pragma unroll
                for (int s = KNN - 1; s > 0; --s) {
                    if (lb[s] < lb[s - 1]) {
                        float t = lb[s]; lb[s] = lb[s - 1]; lb[s - 1] = t;
                    } else break;
                }
            }
        }
    }

    // mean over ascending-sorted 10 (matches jnp.sort[:K] -> sqrt -> mean sum order)
    float acc = 0.0f;
#pragma unroll
    for (int i = 0; i < KNN; i++) acc += sqrtf(lb[i] + 1e-6f);

    g_loss[b * NPTS + n] = acc / 10.0f;
}

__global__ __launch_bounds__(256) void weight_kernel(float* __restrict__ out) {
    __shared__ float red[256];
    const int b = blockIdx.x;
    const int tid = threadIdx.x;
    const float FINF = __int_as_float(0x7f800000);

    float m = FINF;
    for (int i = tid; i < NPTS; i += 256) m = fminf(m, g_loss[b * NPTS + i]);
    red[tid] = m;
    __syncthreads();
#pragma unroll
    for (int s = 128; s > 0; s >>= 1) {
        if (tid < s) red[tid] = fminf(red[tid], red[tid + s]);
        __syncthreads();
    }
    const float minl = red[0];

    for (int i = tid; i < NPTS; i += 256) {
        float t = g_loss[b * NPTS + i] - minl;
        float w = 2.0f / (1.0f + expf(30.0f * t));   // 2*sigmoid(-30*t)
        out[b * NPTS + i] = (w > 0.6f) ? 1.0f : 0.0f;
    }
}

extern "C" void kernel_launch(void* const* d_in, const int* in_sizes, int n_in,
                              void* d_out, int out_size) {
    const float* src = (const float*)d_in[0];
    const float* tgt = (const float*)d_in[1];
    float* out = (float*)d_out;

    const int smem = 7 * NPTS * sizeof(float);   // 56 KB > 48 KB default
    cudaFuncSetAttribute(knn_loss_kernel, cudaFuncAttributeMaxDynamicSharedMemorySize, smem);

    knn_loss_kernel<<<BATCH * 8, 256, smem>>>(src, tgt);
    weight_kernel<<<BATCH, 256>>>(out);
}